// round 2
// baseline (speedup 1.0000x reference)
#include <cuda_runtime.h>

// PatchExtractor3d: out[b, c*27 + i*9 + j*3 + l, d, h, w] = xpad[b, c, d+i, h+j, w+l]
// Shapes: x [2,3,32,128,128] fp32, out [2,81,32,128,128] fp32, pad=1, K=3.
//
// One warp per output row (Wo=128 floats = 32 lanes x float4).
// The w-shift (l-1) is warp-uniform -> aligned LDG.128 + shfl, aligned STG.128.

static constexpr int B_  = 2;
static constexpr int C_  = 3;
static constexpr int D_  = 32;
static constexpr int H_  = 128;
static constexpr int W_  = 128;
static constexpr int COUT = C_ * 27;                 // 81
static constexpr int ROWS = B_ * COUT * D_ * H_;     // 663552 output rows

__global__ __launch_bounds__(256, 8)
void patch3d_kernel(const float* __restrict__ x, float* __restrict__ out) {
    const int warp = (blockIdx.x * blockDim.x + threadIdx.x) >> 5;
    const int lane = threadIdx.x & 31;
    if (warp >= ROWS) return;

    // Decompose row index r = ((b*COUT + co)*D + d)*H + h
    const int r  = warp;
    const int h  = r & (H_ - 1);
    const int d  = (r >> 7) & (D_ - 1);
    const int t  = r >> 12;             // b*COUT + co, max 161
    const int co = t % COUT;
    const int b  = t / COUT;
    const int c   = co / 27;
    const int rem = co - c * 27;
    const int i   = rem / 9;
    const int jl  = rem - i * 9;
    const int j   = jl / 3;
    const int l   = jl - j * 3;

    const int din = d + i - 1;
    const int hin = h + j - 1;

    float4* o4 = reinterpret_cast<float4*>(out) + (size_t)r * (W_ / 4) + lane;

    // Padding row -> all zeros (warp-uniform)
    if ((unsigned)din >= (unsigned)D_ || (unsigned)hin >= (unsigned)H_) {
        *o4 = make_float4(0.f, 0.f, 0.f, 0.f);
        return;
    }

    const size_t in_row = (((size_t)(b * C_ + c) * D_ + din) * H_ + hin) * W_;
    const float4 cur = reinterpret_cast<const float4*>(x + in_row)[lane];

    float4 res;
    if (l == 1) {
        res = cur;                                    // identity shift
    } else if (l == 0) {
        // out[w] = in[w-1]; lane needs prev lane's .w
        const float pw = __shfl_up_sync(0xffffffffu, cur.w, 1);
        res.x = (lane == 0) ? 0.f : pw;
        res.y = cur.x;
        res.z = cur.y;
        res.w = cur.z;
    } else {
        // out[w] = in[w+1]; lane needs next lane's .x
        const float nx = __shfl_down_sync(0xffffffffu, cur.x, 1);
        res.x = cur.y;
        res.y = cur.z;
        res.z = cur.w;
        res.w = (lane == 31) ? 0.f : nx;
    }
    *o4 = res;
}

extern "C" void kernel_launch(void* const* d_in, const int* in_sizes, int n_in,
                              void* d_out, int out_size) {
    const float* x = (const float*)d_in[0];
    float* out = (float*)d_out;
    (void)in_sizes; (void)n_in; (void)out_size;

    const int warps_per_block = 256 / 32;                 // 8 rows per block
    const int blocks = ROWS / warps_per_block;            // 82944, exact
    patch3d_kernel<<<blocks, 256>>>(x, out);
}

// round 3
// speedup vs baseline: 1.0333x; 1.0333x over previous
#include <cuda_runtime.h>

// PatchExtractor3d: out[b, c*27 + i*9 + j*3 + l, d, h, w] = xpad[b, c, d+i, h+j, w+l]
// x [2,3,32,128,128] fp32 -> out [2,81,32,128,128] fp32, pad=1, K=3.
//
// Block = one (b, co, d) plane (128 rows x 128 floats). All of (c,i,j,l,din)
// are block-uniform -> index math once per block. 8 warps x 16 iterations,
// lane handles one float4 per row; w-shift via shfl (branch hoisted by template).

static constexpr int B_  = 2;
static constexpr int C_  = 3;
static constexpr int D_  = 32;
static constexpr int H_  = 128;
static constexpr int W_  = 128;
static constexpr int COUT = C_ * 27;   // 81

template<int L>
__device__ __forceinline__ float4 shift_row(float4 cur, int lane) {
    if (L == 1) return cur;
    float4 r;
    if (L == 0) {                       // out[w] = in[w-1]
        const float pw = __shfl_up_sync(0xffffffffu, cur.w, 1);
        r.x = (lane == 0) ? 0.f : pw;
        r.y = cur.x; r.z = cur.y; r.w = cur.z;
    } else {                            // out[w] = in[w+1]
        const float nx = __shfl_down_sync(0xffffffffu, cur.x, 1);
        r.x = cur.y; r.y = cur.z; r.z = cur.w;
        r.w = (lane == 31) ? 0.f : nx;
    }
    return r;
}

template<int L>
__device__ __forceinline__ void do_plane(const float* __restrict__ xplane,
                                         float4* __restrict__ o4,
                                         int warp, int lane, int j) {
    // warp handles rows h = warp, warp+8, ..., warp+120
    #pragma unroll
    for (int it = 0; it < 16; ++it) {
        const int h   = warp + it * 8;
        const int hin = h + j - 1;              // hin bound is the only per-row check
        float4 res;
        if ((unsigned)hin >= (unsigned)H_) {    // warp-uniform (h uniform in warp)
            res = make_float4(0.f, 0.f, 0.f, 0.f);
        } else {
            const float4 cur =
                reinterpret_cast<const float4*>(xplane + (size_t)hin * W_)[lane];
            res = shift_row<L>(cur, lane);
        }
        o4[(size_t)h * (W_ / 4)] = res;
    }
}

__global__ __launch_bounds__(256, 8)
void patch3d_kernel(const float* __restrict__ x, float* __restrict__ out) {
    const int d    = blockIdx.x;       // 0..31
    const int co   = blockIdx.y;       // 0..80
    const int b    = blockIdx.z;       // 0..1
    const int warp = threadIdx.x >> 5;
    const int lane = threadIdx.x & 31;

    // Block-uniform decomposition (uniform datapath, once per block)
    const int c   = co / 27;
    const int rem = co - c * 27;
    const int i   = rem / 9;
    const int jl  = rem - i * 9;
    const int j   = jl / 3;
    const int l   = jl - j * 3;
    const int din = d + i - 1;

    float4* o4 = reinterpret_cast<float4*>(out)
               + ((size_t)((b * COUT + co) * D_ + d) * H_) * (W_ / 4) + lane;

    if ((unsigned)din >= (unsigned)D_) {
        // whole plane is padding -> pure zero-store loop
        const float4 z = make_float4(0.f, 0.f, 0.f, 0.f);
        #pragma unroll
        for (int it = 0; it < 16; ++it)
            o4[(size_t)(warp + it * 8) * (W_ / 4)] = z;
        return;
    }

    const float* xplane = x + (((size_t)(b * C_ + c) * D_ + din) * H_) * W_;

    if (l == 0)      do_plane<0>(xplane, o4, warp, lane, j);
    else if (l == 1) do_plane<1>(xplane, o4, warp, lane, j);
    else             do_plane<2>(xplane, o4, warp, lane, j);
}

extern "C" void kernel_launch(void* const* d_in, const int* in_sizes, int n_in,
                              void* d_out, int out_size) {
    const float* x = (const float*)d_in[0];
    float* out = (float*)d_out;
    (void)in_sizes; (void)n_in; (void)out_size;

    dim3 grid(D_, COUT, B_);           // (32, 81, 2) = 5184 blocks
    patch3d_kernel<<<grid, 256>>>(x, out);
}

// round 5
// speedup vs baseline: 1.1929x; 1.1544x over previous
#include <cuda_runtime.h>

// PatchExtractor3d: out[b, c*27 + i*9 + j*3 + l, d, h, w] = xpad[b, c, d+i, h+j, w+l]
// x [2,3,32,128,128] fp32 -> out [2,81,32,128,128] fp32, pad=1, K=3.
//
// Block = one (b, co, d) plane. Index math block-uniform. Each warp: 16 rows,
// processed as 2 batches of 8 front-loaded LDG.128 (MLP=8), then shfl+STG.128.
// __launch_bounds__(256,4) -> 64-reg budget so the 8 float4s stay live.

static constexpr int B_  = 2;
static constexpr int C_  = 3;
static constexpr int D_  = 32;
static constexpr int H_  = 128;
static constexpr int W_  = 128;
static constexpr int COUT = C_ * 27;   // 81

template<int L>
__device__ __forceinline__ float4 shift_row(float4 cur, int lane) {
    if (L == 1) return cur;
    float4 r;
    if (L == 0) {                       // out[w] = in[w-1]
        const float pw = __shfl_up_sync(0xffffffffu, cur.w, 1);
        r.x = (lane == 0) ? 0.f : pw;
        r.y = cur.x; r.z = cur.y; r.w = cur.z;
    } else {                            // out[w] = in[w+1]
        const float nx = __shfl_down_sync(0xffffffffu, cur.x, 1);
        r.x = cur.y; r.y = cur.z; r.z = cur.w;
        r.w = (lane == 31) ? 0.f : nx;
    }
    return r;
}

template<int L>
__device__ __forceinline__ void do_plane(const float* __restrict__ xplane,
                                         float4* __restrict__ o4,
                                         int warp, int lane, int j) {
    // warp handles rows h = warp + it*8, it = 0..15, in 2 batches of 8
    #pragma unroll
    for (int bat = 0; bat < 2; ++bat) {
        float4 v[8];
        // Phase 1: front-batched loads (predicated zero at the h-boundary)
        #pragma unroll
        for (int k = 0; k < 8; ++k) {
            const int h   = warp + (bat * 8 + k) * 8;
            const int hin = h + j - 1;
            if ((unsigned)hin < (unsigned)H_) {
                const float4* p =
                    reinterpret_cast<const float4*>(xplane + (size_t)hin * W_) + lane;
                v[k] = __ldg(p);
            } else {
                v[k] = make_float4(0.f, 0.f, 0.f, 0.f);
            }
        }
        // Phase 2: shift + streaming stores
        #pragma unroll
        for (int k = 0; k < 8; ++k) {
            const int h = warp + (bat * 8 + k) * 8;
            __stcs(o4 + (size_t)h * (W_ / 4), shift_row<L>(v[k], lane));
        }
    }
}

__global__ __launch_bounds__(256, 4)
void patch3d_kernel(const float* __restrict__ x, float* __restrict__ out) {
    const int d    = blockIdx.x;       // 0..31
    const int co   = blockIdx.y;       // 0..80
    const int b    = blockIdx.z;       // 0..1
    const int warp = threadIdx.x >> 5;
    const int lane = threadIdx.x & 31;

    // Block-uniform decomposition
    const int c   = co / 27;
    const int rem = co - c * 27;
    const int i   = rem / 9;
    const int jl  = rem - i * 9;
    const int j   = jl / 3;
    const int l   = jl - j * 3;
    const int din = d + i - 1;

    float4* o4 = reinterpret_cast<float4*>(out)
               + ((size_t)((b * COUT + co) * D_ + d) * H_) * (W_ / 4) + lane;

    if ((unsigned)din >= (unsigned)D_) {
        // whole plane is padding -> pure zero-store loop
        const float4 z = make_float4(0.f, 0.f, 0.f, 0.f);
        #pragma unroll
        for (int it = 0; it < 16; ++it)
            __stcs(o4 + (size_t)(warp + it * 8) * (W_ / 4), z);
        return;
    }

    const float* xplane = x + (((size_t)(b * C_ + c) * D_ + din) * H_) * W_;

    if (l == 0)      do_plane<0>(xplane, o4, warp, lane, j);
    else if (l == 1) do_plane<1>(xplane, o4, warp, lane, j);
    else             do_plane<2>(xplane, o4, warp, lane, j);
}

extern "C" void kernel_launch(void* const* d_in, const int* in_sizes, int n_in,
                              void* d_out, int out_size) {
    const float* x = (const float*)d_in[0];
    float* out = (float*)d_out;
    (void)in_sizes; (void)n_in; (void)out_size;

    dim3 grid(D_, COUT, B_);           // (32, 81, 2) = 5184 blocks
    patch3d_kernel<<<grid, 256>>>(x, out);
}

// round 6
// speedup vs baseline: 1.2177x; 1.0208x over previous
#include <cuda_runtime.h>

// PatchExtractor3d: out[b, c*27 + i*9 + j*3 + l, d, h, w] = xpad[b, c, d+i, h+j, w+l]
// x [2,3,32,128,128] fp32 -> out [2,81,32,128,128] fp32, pad=1, K=3.
//
// Block = one (b, co, d) plane. Index math block-uniform. Each warp: its full
// 16-row slab front-loaded as 16 independent LDG.128 (MLP_p1=16, 64 data regs),
// then 16x shfl+STG.128 streaming stores. __launch_bounds__(256,3) -> 84-reg budget.

static constexpr int B_  = 2;
static constexpr int C_  = 3;
static constexpr int D_  = 32;
static constexpr int H_  = 128;
static constexpr int W_  = 128;
static constexpr int COUT = C_ * 27;   // 81

template<int L>
__device__ __forceinline__ float4 shift_row(float4 cur, int lane) {
    if (L == 1) return cur;
    float4 r;
    if (L == 0) {                       // out[w] = in[w-1]
        const float pw = __shfl_up_sync(0xffffffffu, cur.w, 1);
        r.x = (lane == 0) ? 0.f : pw;
        r.y = cur.x; r.z = cur.y; r.w = cur.z;
    } else {                            // out[w] = in[w+1]
        const float nx = __shfl_down_sync(0xffffffffu, cur.x, 1);
        r.x = cur.y; r.y = cur.z; r.z = cur.w;
        r.w = (lane == 31) ? 0.f : nx;
    }
    return r;
}

template<int L>
__device__ __forceinline__ void do_plane(const float* __restrict__ xplane,
                                         float4* __restrict__ o4,
                                         int warp, int lane, int j) {
    // warp handles rows h = warp + it*8, it = 0..15
    float4 v[16];
    // Phase 1: 16 front-batched independent loads (max MLP)
    #pragma unroll
    for (int k = 0; k < 16; ++k) {
        const int h   = warp + k * 8;
        const int hin = h + j - 1;
        if ((unsigned)hin < (unsigned)H_) {
            const float4* p =
                reinterpret_cast<const float4*>(xplane + (size_t)hin * W_) + lane;
            v[k] = __ldg(p);
        } else {
            v[k] = make_float4(0.f, 0.f, 0.f, 0.f);
        }
    }
    // Phase 2: shift + streaming stores
    #pragma unroll
    for (int k = 0; k < 16; ++k) {
        const int h = warp + k * 8;
        __stcs(o4 + (size_t)h * (W_ / 4), shift_row<L>(v[k], lane));
    }
}

__global__ __launch_bounds__(256, 3)
void patch3d_kernel(const float* __restrict__ x, float* __restrict__ out) {
    const int d    = blockIdx.x;       // 0..31
    const int co   = blockIdx.y;       // 0..80
    const int b    = blockIdx.z;       // 0..1
    const int warp = threadIdx.x >> 5;
    const int lane = threadIdx.x & 31;

    // Block-uniform decomposition
    const int c   = co / 27;
    const int rem = co - c * 27;
    const int i   = rem / 9;
    const int jl  = rem - i * 9;
    const int j   = jl / 3;
    const int l   = jl - j * 3;
    const int din = d + i - 1;

    float4* o4 = reinterpret_cast<float4*>(out)
               + ((size_t)((b * COUT + co) * D_ + d) * H_) * (W_ / 4) + lane;

    if ((unsigned)din >= (unsigned)D_) {
        // whole plane is padding -> pure zero-store loop
        const float4 z = make_float4(0.f, 0.f, 0.f, 0.f);
        #pragma unroll
        for (int it = 0; it < 16; ++it)
            __stcs(o4 + (size_t)(warp + it * 8) * (W_ / 4), z);
        return;
    }

    const float* xplane = x + (((size_t)(b * C_ + c) * D_ + din) * H_) * W_;

    if (l == 0)      do_plane<0>(xplane, o4, warp, lane, j);
    else if (l == 1) do_plane<1>(xplane, o4, warp, lane, j);
    else             do_plane<2>(xplane, o4, warp, lane, j);
}

extern "C" void kernel_launch(void* const* d_in, const int* in_sizes, int n_in,
                              void* d_out, int out_size) {
    const float* x = (const float*)d_in[0];
    float* out = (float*)d_out;
    (void)in_sizes; (void)n_in; (void)out_size;

    dim3 grid(D_, COUT, B_);           // (32, 81, 2) = 5184 blocks
    patch3d_kernel<<<grid, 256>>>(x, out);
}